// round 2
// baseline (speedup 1.0000x reference)
#include <cuda_runtime.h>

// PGD step: y = max(d + LR*sqrt(r*g)*rsqrt(max(d,EPS)), 0)
// then water-filling projection onto {x>=0, c@x <= Q}: 25-step bisection on
// the water level lambda. One CTA per row; y and c live in registers.

#define NCOL  4096
#define BLK   256
#define VPT   16
#define V4    4
#define QBUD  100.0f
#define LRC   0.05f
#define NITER 25
#define NWARP (BLK / 32)

__device__ __forceinline__ float warpSum(float v) {
#pragma unroll
    for (int o = 16; o; o >>= 1) v += __shfl_down_sync(0xffffffffu, v, o);
    return v;
}
__device__ __forceinline__ float warpMax(float v) {
#pragma unroll
    for (int o = 16; o; o >>= 1) v = fmaxf(v, __shfl_down_sync(0xffffffffu, v, o));
    return v;
}

__global__ __launch_bounds__(BLK) void pgd_knap_kernel(
    const float4* __restrict__ r4,
    const float4* __restrict__ d4,
    const float4* __restrict__ g4,
    const float4* __restrict__ c4,
    float4* __restrict__ o4)
{
    const int row  = blockIdx.x;
    const int t    = threadIdx.x;
    const int wid  = t >> 5;
    const int lane = t & 31;
    const size_t base = (size_t)row * (NCOL / 4);

    // parity double-buffered per-warp partials: no trailing barrier needed
    __shared__ float swarp[2][NWARP];
    __shared__ float smax[NWARP];

    float y[VPT];
    float cc[VPT];

    // ---- Load + gradient step + per-thread partials ----
    float pcost = 0.0f;
    float pmax  = 0.0f;
#pragma unroll
    for (int i = 0; i < V4; i++) {
        const int idx = t + i * BLK;
        float4 R = r4[base + idx];
        float4 D = d4[base + idx];
        float4 G = g4[idx];
        float4 C = c4[idx];
        float rr[4] = {R.x, R.y, R.z, R.w};
        float dd[4] = {D.x, D.y, D.z, D.w};
        float gg[4] = {G.x, G.y, G.z, G.w};
        float cv[4] = {C.x, C.y, C.z, C.w};
#pragma unroll
        for (int j = 0; j < 4; j++) {
            float u  = rr[j] * gg[j];
            float dm = fmaxf(dd[j], 1e-12f);
            float v  = fmaf(LRC, sqrtf(u) * rsqrtf(dm), dd[j]);
            float yv = fmaxf(v, 0.0f);
            y[i * 4 + j]  = yv;
            cc[i * 4 + j] = cv[j];
            pcost = fmaf(yv, cv[j], pcost);
            pmax  = fmaxf(pmax, yv / cv[j]);
        }
    }

    // ---- Block reduction: total cost (sum) and lam_hi seed (max) ----
    pcost = warpSum(pcost);
    pmax  = warpMax(pmax);
    if (lane == 0) {
        swarp[0][wid] = pcost;
        smax[wid]     = pmax;
    }
    __syncthreads();

    float cost = 0.0f, hi = 0.0f;
#pragma unroll
    for (int w = 0; w < NWARP; w++) {
        cost += swarp[0][w];
        hi    = fmaxf(hi, smax[w]);
    }

    const bool violate = (cost > QBUD);
    float lam_lo = 0.0f;
    float lam_hi = hi;

    // ---- 25-iteration bisection: 1 barrier per iteration ----
    if (violate) {
#pragma unroll 1
        for (int it = 0; it < NITER; it++) {
            const float lam = 0.5f * (lam_lo + lam_hi);
            float p = 0.0f;
#pragma unroll
            for (int i = 0; i < VPT; i++) {
                float tv = fmaxf(fmaf(-lam, cc[i], y[i]), 0.0f);
                p = fmaf(tv, cc[i], p);
            }
            p = warpSum(p);
            const int buf = (it + 1) & 1;   // alternate buffers each iter
            if (lane == 0) swarp[buf][wid] = p;
            __syncthreads();
            float tot = 0.0f;
#pragma unroll
            for (int w = 0; w < NWARP; w++) tot += swarp[buf][w];
            // uniform decision, computed redundantly by every thread
            if (tot - QBUD > 0.0f) lam_lo = lam; else lam_hi = lam;
        }
    }

    // ---- Final projection + coalesced store ----
#pragma unroll
    for (int i = 0; i < V4; i++) {
        float4 O;
        float* op = (float*)&O;
#pragma unroll
        for (int j = 0; j < 4; j++) {
            const float yv = y[i * 4 + j];
            const float cv = cc[i * 4 + j];
            op[j] = violate ? fmaxf(fmaf(-lam_hi, cv, yv), 0.0f) : yv;
        }
        o4[base + t + i * BLK] = O;
    }
}

extern "C" void kernel_launch(void* const* d_in, const int* in_sizes, int n_in,
                              void* d_out, int out_size) {
    const float* r = (const float*)d_in[0];
    const float* d = (const float*)d_in[1];
    const float* g = (const float*)d_in[2];
    const float* c = (const float*)d_in[3];
    const int n = in_sizes[2];          // N = 4096
    const int b = in_sizes[0] / n;      // B = 16384
    pgd_knap_kernel<<<b, BLK>>>(
        (const float4*)r, (const float4*)d,
        (const float4*)g, (const float4*)c,
        (float4*)d_out);
}

// round 5
// speedup vs baseline: 1.6081x; 1.6081x over previous
#include <cuda_runtime.h>

// PGD step: y = max(d + LR*sqrt(r*g)*rsqrt(max(d,EPS)), 0)
// Projection onto {x>=0, c@x <= Q} via exact active-set Newton iteration on
// the water level:  lam' = (sum_{t_i>lam} a_i t_i - Q) / sum_{t_i>lam} a_i
// with t_i = y_i/c_i, a_i = c_i^2. Monotone, finite, exact at convergence.
// One CTA per row; t, c, a live in registers (16 per thread).

#define NCOL  4096
#define BLK   256
#define VPT   16
#define V4    4
#define QBUD  100.0f
#define LRC   0.05f
#define NWARP (BLK / 32)
#define MAXIT 50

__device__ __forceinline__ float warpSum(float v) {
#pragma unroll
    for (int o = 16; o; o >>= 1) v += __shfl_down_sync(0xffffffffu, v, o);
    return v;
}

__global__ __launch_bounds__(BLK) void pgd_newton_kernel(
    const float4* __restrict__ r4,
    const float4* __restrict__ d4,
    const float4* __restrict__ g4,
    const float4* __restrict__ c4,
    float4* __restrict__ o4)
{
    const int row  = blockIdx.x;
    const int t    = threadIdx.x;
    const int wid  = t >> 5;
    const int lane = t & 31;
    const size_t base = (size_t)row * (NCOL / 4);

    // parity double-buffered per-warp partials (two sums per round)
    __shared__ float ssb[2][NWARP];
    __shared__ float ssa[2][NWARP];

    float tv[VPT];   // t_i = y_i / c_i
    float cv[VPT];   // c_i
    float av[VPT];   // a_i = c_i^2

    // ---- Load + gradient step; first Newton sums at lam=0 (all active) ----
    float pb = 0.0f;   // sum a_i * t_i  (== sum y_i c_i == cost)
    float pa = 0.0f;   // sum a_i
#pragma unroll
    for (int i = 0; i < V4; i++) {
        const int idx = t + i * BLK;
        float4 R = r4[base + idx];
        float4 D = d4[base + idx];
        float4 G = g4[idx];
        float4 C = c4[idx];
        float rr[4] = {R.x, R.y, R.z, R.w};
        float dd[4] = {D.x, D.y, D.z, D.w};
        float gg[4] = {G.x, G.y, G.z, G.w};
        float cf[4] = {C.x, C.y, C.z, C.w};
#pragma unroll
        for (int j = 0; j < 4; j++) {
            float u  = rr[j] * gg[j];
            float dm = fmaxf(dd[j], 1e-12f);
            float yv = fmaxf(fmaf(LRC, sqrtf(u) * rsqrtf(dm), dd[j]), 0.0f);
            float c  = cf[j];
            float ti = __fdividef(yv, c);
            float ai = c * c;
            const int k = i * 4 + j;
            tv[k] = ti; cv[k] = c; av[k] = ai;
            pb = fmaf(ai, ti, pb);
            pa += ai;
        }
    }

    pb = warpSum(pb);
    pa = warpSum(pa);
    if (lane == 0) { ssb[0][wid] = pb; ssa[0][wid] = pa; }
    __syncthreads();
    float SB = 0.0f, SA = 0.0f;
#pragma unroll
    for (int w = 0; w < NWARP; w++) { SB += ssb[0][w]; SA += ssa[0][w]; }

    float lam = 0.0f;
    if (SB > QBUD) {
        lam = __fdividef(SB - QBUD, SA);
        // ---- active-set Newton loop (CTA-uniform, exact finite termination) ----
#pragma unroll 1
        for (int it = 0; it < MAXIT; it++) {
            pb = 0.0f; pa = 0.0f;
#pragma unroll
            for (int k = 0; k < VPT; k++) {
                if (tv[k] > lam) {
                    pa += av[k];
                    pb = fmaf(av[k], tv[k], pb);
                }
            }
            pb = warpSum(pb);
            pa = warpSum(pa);
            const int buf = (it & 1) ^ 1;
            if (lane == 0) { ssb[buf][wid] = pb; ssa[buf][wid] = pa; }
            __syncthreads();
            SB = 0.0f; SA = 0.0f;
#pragma unroll
            for (int w = 0; w < NWARP; w++) { SB += ssb[buf][w]; SA += ssa[buf][w]; }
            if (!(SA > 0.0f)) break;                 // degenerate guard
            float ln = __fdividef(SB - QBUD, SA);
            if (!(ln > lam)) break;                  // fixed point: active set stable
            lam = ln;
        }
    }

    // ---- Final projection + coalesced store: out = c * max(t - lam, 0) ----
#pragma unroll
    for (int i = 0; i < V4; i++) {
        float4 O;
        float* op = (float*)&O;
#pragma unroll
        for (int j = 0; j < 4; j++) {
            const int k = i * 4 + j;
            op[j] = cv[k] * fmaxf(tv[k] - lam, 0.0f);
        }
        o4[base + t + i * BLK] = O;
    }
}

extern "C" void kernel_launch(void* const* d_in, const int* in_sizes, int n_in,
                              void* d_out, int out_size) {
    const float* r = (const float*)d_in[0];
    const float* d = (const float*)d_in[1];
    const float* g = (const float*)d_in[2];
    const float* c = (const float*)d_in[3];
    const int n = in_sizes[2];          // N = 4096
    const int b = in_sizes[0] / n;      // B = 16384
    pgd_newton_kernel<<<b, BLK>>>(
        (const float4*)r, (const float4*)d,
        (const float4*)g, (const float4*)c,
        (float4*)d_out);
}